// round 13
// baseline (speedup 1.0000x reference)
#include <cuda_runtime.h>
#include <cstdint>

// Problem constants (fixed by the dataset generator).
#define NN   40000
#define EE   640000
#define FIN  128
#define FHID 512
#define FOUT 256

#define SCAN_BLOCKS ((NN + 255) / 256)   // 157

// ---------------- scratch (static device globals; no allocation allowed) ----
__device__ int   g_is64;
__device__ int   g_cnt[NN];
__device__ int   g_rowptr[NN + 1];
__device__ int   g_cursor[NN];
__device__ int   g_col[EE];
__device__ float g_xr  [(size_t)NN * FIN];   // tf32-rounded copy of x   (20 MB)
__device__ float g_aggA[(size_t)NN * FIN];   // mean-aggregated x        (20 MB)
__device__ float g_h   [(size_t)NN * FHID];  // layer-1 output           (82 MB)
__device__ float g_p   [(size_t)NN * FOUT];  // h @ W2l                  (40 MB)
__device__ float g_q   [(size_t)NN * FOUT];  // h @ W2r + b2             (40 MB)
// transposed (and tf32-rounded) weights [N,K]
__device__ float g_Wt1l[FHID * FIN];
__device__ float g_Wt1r[FHID * FIN];
__device__ float g_Wt2lr[2 * FOUT * FHID];   // rows 0-255: W2l^T, 256-511: W2r^T

__device__ __forceinline__ float tf32r(float f) {
    uint32_t u;
    asm("cvt.rna.tf32.f32 %0, %1;" : "=r"(u) : "f"(f));
    return __uint_as_float(u);
}
__device__ __forceinline__ int edge_at(const int* __restrict__ ei, int is64, size_t idx) {
    return is64 ? (int)((const long long*)ei)[idx] : ei[idx];
}

// ---------------- CSR build --------------------------------------------------
// hist also performs edge-dtype detection (thread 0 of block 0; g_cnt indices
// are guaranteed < NN under either interpretation only after detection, so
// detection runs in a guarded prefix: block 0 thread 0 writes g_is64, then all
// threads of that block proceed after a syncthreads; other blocks spin-read.
// Simpler and safe: detection is done in a tiny prologue inside hist block 0,
// all other blocks derive is64 themselves from the same 64 words (cheap, L2).
__device__ __forceinline__ int detect_is64(const int* __restrict__ ei32) {
    int all0 = 1;
#pragma unroll
    for (int k = 0; k < 64; k++)
        if (__ldg(&ei32[2 * k + 1]) != 0) all0 = 0;
    return all0;
}
__global__ void hist_kernel(const int* __restrict__ ei) {
    __shared__ int s_is64;
    if (threadIdx.x == 0) s_is64 = detect_is64(ei);
    __syncthreads();
    int is64 = s_is64;
    if (blockIdx.x == 0 && threadIdx.x == 0) g_is64 = is64;  // for fill/others
    int e = blockIdx.x * blockDim.x + threadIdx.x;
    if (e < EE) atomicAdd(&g_cnt[edge_at(ei, is64, (size_t)EE + e)], 1);
}

// Fused exclusive scan: each block redundantly computes its prefix over
// g_cnt[0, b*256) (L2-resident, ~3M reads total), then scans its own 256.
__global__ void scan_fused() {
    __shared__ int red[256];
    __shared__ int sh[256];
    int b = blockIdx.x, t = threadIdx.x;

    int lim = b * 256;
    int pre = 0;
    for (int i = t; i < lim; i += 256) pre += g_cnt[i];
    red[t] = pre;
    __syncthreads();
    for (int off = 128; off > 0; off >>= 1) {
        if (t < off) red[t] += red[t + off];
        __syncthreads();
    }
    int blockoff = red[0];

    int i = lim + t;
    int v = (i < NN) ? g_cnt[i] : 0;
    sh[t] = v;
    __syncthreads();
    for (int off = 1; off < 256; off <<= 1) {
        int u = (t >= off) ? sh[t - off] : 0;
        __syncthreads();
        sh[t] += u;
        __syncthreads();
    }
    int excl = sh[t] - v + blockoff;
    if (i < NN) {
        g_rowptr[i] = excl;
        g_cursor[i] = excl;
    }
    if (b == 0 && t == 0) g_rowptr[NN] = EE;
}

__global__ void fill_kernel(const int* __restrict__ ei) {
    int e = blockIdx.x * blockDim.x + threadIdx.x;
    if (e < EE) {
        int is64 = g_is64;
        int d = edge_at(ei, is64, (size_t)EE + e);
        int s = edge_at(ei, is64, (size_t)e);
        int pos = atomicAdd(&g_cursor[d], 1);
        g_col[pos] = s;
    }
}

// ---------------- fused weight prep: transpose + tf32 round -------------------
#define W1_ELEMS (FIN * FHID)
#define W2_ELEMS (FHID * FOUT)
__global__ void prep_weights(const float* __restrict__ W1l, const float* __restrict__ W1r,
                             const float* __restrict__ W2l, const float* __restrict__ W2r) {
    int idx = blockIdx.x * blockDim.x + threadIdx.x;
    if (idx < W1_ELEMS) {
        int k = idx / FHID, n = idx % FHID;
        g_Wt1l[(size_t)n * FIN + k] = tf32r(W1l[idx]);
        return;
    }
    idx -= W1_ELEMS;
    if (idx < W1_ELEMS) {
        int k = idx / FHID, n = idx % FHID;
        g_Wt1r[(size_t)n * FIN + k] = tf32r(W1r[idx]);
        return;
    }
    idx -= W1_ELEMS;
    if (idx < W2_ELEMS) {
        int k = idx / FOUT, n = idx % FOUT;
        g_Wt2lr[(size_t)n * FHID + k] = tf32r(W2l[idx]);
        return;
    }
    idx -= W2_ELEMS;
    if (idx < W2_ELEMS) {
        int k = idx / FOUT, n = idx % FOUT;
        g_Wt2lr[(size_t)(n + FOUT) * FHID + k] = tf32r(W2r[idx]);
    }
}
#define PREP_TOT (2 * W1_ELEMS + 2 * W2_ELEMS)

// ---------------- layer-1 aggregation (warp per node, fp32 gather) ------------
__global__ void __launch_bounds__(256)
agg1_kernel(const float* __restrict__ x, float* __restrict__ aggA,
            float* __restrict__ xr) {
    int node = blockIdx.x * (blockDim.x >> 5) + (threadIdx.x >> 5);
    if (node >= NN) return;
    int lane = threadIdx.x & 31;
    int beg = g_rowptr[node];
    int end = g_rowptr[node + 1];

    const float4* fb = (const float4*)x;   // row = 32 float4
    float4 acc = make_float4(0.f, 0.f, 0.f, 0.f);

    int j = beg;
    for (; j + 3 < end; j += 4) {
        int s0 = __ldg(&g_col[j + 0]);
        int s1 = __ldg(&g_col[j + 1]);
        int s2 = __ldg(&g_col[j + 2]);
        int s3 = __ldg(&g_col[j + 3]);
        float4 a0 = fb[(size_t)s0 * 32 + lane];
        float4 a1 = fb[(size_t)s1 * 32 + lane];
        float4 a2 = fb[(size_t)s2 * 32 + lane];
        float4 a3 = fb[(size_t)s3 * 32 + lane];
        acc.x += (a0.x + a1.x) + (a2.x + a3.x);
        acc.y += (a0.y + a1.y) + (a2.y + a3.y);
        acc.z += (a0.z + a1.z) + (a2.z + a3.z);
        acc.w += (a0.w + a1.w) + (a2.w + a3.w);
    }
    for (; j < end; j++) {
        int s0 = __ldg(&g_col[j]);
        float4 a = fb[(size_t)s0 * 32 + lane];
        acc.x += a.x; acc.y += a.y; acc.z += a.z; acc.w += a.w;
    }
    float inv = 1.0f / (float)max(end - beg, 1);
    acc.x = tf32r(acc.x * inv); acc.y = tf32r(acc.y * inv);
    acc.z = tf32r(acc.z * inv); acc.w = tf32r(acc.w * inv);
    ((float4*)aggA)[(size_t)node * 32 + lane] = acc;

    float4 v = fb[(size_t)node * 32 + lane];
    v.x = tf32r(v.x); v.y = tf32r(v.y); v.z = tf32r(v.z); v.w = tf32r(v.w);
    ((float4*)xr)[(size_t)node * 32 + lane] = v;
}

// ---------------- layer-2 aggregation (warp per node, fp32, +q residual) ------
__global__ void __launch_bounds__(256)
agg2_kernel(const float* __restrict__ p, const float* __restrict__ q,
            float* __restrict__ out) {
    int node = blockIdx.x * (blockDim.x >> 5) + (threadIdx.x >> 5);
    if (node >= NN) return;
    int lane = threadIdx.x & 31;
    int beg = g_rowptr[node];
    int end = g_rowptr[node + 1];

    const float4* fb = (const float4*)p;   // row = 64 float4
    float4 acc0 = make_float4(0.f, 0.f, 0.f, 0.f);
    float4 acc1 = make_float4(0.f, 0.f, 0.f, 0.f);

    int j = beg;
    for (; j + 3 < end; j += 4) {
        int s0 = __ldg(&g_col[j + 0]);
        int s1 = __ldg(&g_col[j + 1]);
        int s2 = __ldg(&g_col[j + 2]);
        int s3 = __ldg(&g_col[j + 3]);
        const float4* r0 = fb + (size_t)s0 * 64;
        const float4* r1 = fb + (size_t)s1 * 64;
        const float4* r2 = fb + (size_t)s2 * 64;
        const float4* r3 = fb + (size_t)s3 * 64;
        float4 a0 = r0[lane],      b0 = r1[lane],      c0 = r2[lane],      d0 = r3[lane];
        float4 a1 = r0[lane + 32], b1 = r1[lane + 32], c1 = r2[lane + 32], d1 = r3[lane + 32];
        acc0.x += (a0.x + b0.x) + (c0.x + d0.x);
        acc0.y += (a0.y + b0.y) + (c0.y + d0.y);
        acc0.z += (a0.z + b0.z) + (c0.z + d0.z);
        acc0.w += (a0.w + b0.w) + (c0.w + d0.w);
        acc1.x += (a1.x + b1.x) + (c1.x + d1.x);
        acc1.y += (a1.y + b1.y) + (c1.y + d1.y);
        acc1.z += (a1.z + b1.z) + (c1.z + d1.z);
        acc1.w += (a1.w + b1.w) + (c1.w + d1.w);
    }
    for (; j < end; j++) {
        int s0 = __ldg(&g_col[j]);
        const float4* r0 = fb + (size_t)s0 * 64;
        float4 a0 = r0[lane], a1 = r0[lane + 32];
        acc0.x += a0.x; acc0.y += a0.y; acc0.z += a0.z; acc0.w += a0.w;
        acc1.x += a1.x; acc1.y += a1.y; acc1.z += a1.z; acc1.w += a1.w;
    }
    float inv = 1.0f / (float)max(end - beg, 1);
    const float4* qv = (const float4*)(q + (size_t)node * FOUT);
    float4* ov = (float4*)(out + (size_t)node * FOUT);
    float4 q0 = qv[lane], q1 = qv[lane + 32];
    float4 o0, o1;
    o0.x = acc0.x * inv + q0.x; o0.y = acc0.y * inv + q0.y;
    o0.z = acc0.z * inv + q0.z; o0.w = acc0.w * inv + q0.w;
    o1.x = acc1.x * inv + q1.x; o1.y = acc1.y * inv + q1.y;
    o1.z = acc1.z * inv + q1.z; o1.w = acc1.w * inv + q1.w;
    ov[lane]      = o0;
    ov[lane + 32] = o1;
}

// ================= tf32 mma.sync GEMM, BM=128 x BN=256, 3-stage ==============
#define G_BM 128
#define G_BN 256
#define G_BK 32
#define G_STAGES 3
#define G_PAD_STRIDE 36
#define G_A_BYTES (G_BM * G_PAD_STRIDE * 4)
#define G_B_BYTES (G_BN * G_PAD_STRIDE * 4)
#define G_STAGE_BYTES (G_A_BYTES + G_B_BYTES)
#define G_SMEM_SZ (G_STAGES * G_STAGE_BYTES)

__device__ __forceinline__ uint32_t smem_u32(const void* p) {
    uint32_t a;
    asm("{ .reg .u64 t; cvta.to.shared.u64 t, %1; cvt.u32.u64 %0, t; }"
        : "=r"(a) : "l"(p));
    return a;
}
__device__ __forceinline__ void cp_async16(uint32_t dst, const void* src, int src_bytes) {
    asm volatile("cp.async.ca.shared.global [%0], [%1], 16, %2;"
                 :: "r"(dst), "l"(src), "r"(src_bytes) : "memory");
}
__device__ __forceinline__ void cp_commit() {
    asm volatile("cp.async.commit_group;" ::: "memory");
}
template <int NPEND>
__device__ __forceinline__ void cp_wait() {
    asm volatile("cp.async.wait_group %0;" :: "n"(NPEND) : "memory");
}
__device__ __forceinline__ void mma_tf32(float* d, const uint32_t* a, const uint32_t* b) {
    asm volatile(
        "mma.sync.aligned.m16n8k8.row.col.f32.tf32.tf32.f32 "
        "{%0,%1,%2,%3}, {%4,%5,%6,%7}, {%8,%9}, {%0,%1,%2,%3};"
        : "+f"(d[0]), "+f"(d[1]), "+f"(d[2]), "+f"(d[3])
        : "r"(a[0]), "r"(a[1]), "r"(a[2]), "r"(a[3]), "r"(b[0]), "r"(b[1]));
}
__device__ __forceinline__ void ldsm_x4(uint32_t& d0, uint32_t& d1, uint32_t& d2,
                                        uint32_t& d3, uint32_t addr) {
    asm volatile("ldmatrix.sync.aligned.m8n8.x4.shared.b16 {%0,%1,%2,%3}, [%4];"
                 : "=r"(d0), "=r"(d1), "=r"(d2), "=r"(d3) : "r"(addr));
}

template <int ROWS>
__device__ __forceinline__ void issue_tile(
    const float* __restrict__ src, int row0, int row_lim, int K, int k0,
    uint32_t dst_base, int tid) {
#pragma unroll
    for (int u = 0; u < (ROWS * 8) / 512; u++) {
        int id  = u * 512 + tid;
        int row = id >> 3;
        int c   = id & 7;
        int gr  = row0 + row;
        int ok  = gr < row_lim;
        const float* s = src + (size_t)(ok ? gr : (row_lim - 1)) * K + k0 + c * 4;
        cp_async16(dst_base + row * (G_PAD_STRIDE * 4) + c * 16, s, ok ? 16 : 0);
    }
}

__global__ void __launch_bounds__(512, 1)
gemm_tf32_kernel(const float* __restrict__ A1, const float* __restrict__ B1t, int K1,
                 const float* __restrict__ A2, const float* __restrict__ B2t, int K2,
                 const float* __restrict__ bias,
                 float* __restrict__ C, float* __restrict__ C2,
                 int M, int N, int relu, int round_out, int split_n) {
    extern __shared__ float smem[];
    uint32_t sb = smem_u32(smem);

    int tid  = threadIdx.x;
    int lane = tid & 31;
    int wid  = tid >> 5;
    int wm   = wid & 3;
    int wn   = wid >> 2;
    int m0 = blockIdx.y * G_BM;
    int n0 = blockIdx.x * G_BN;

    const int kt1 = K1 >> 5;
    const int KT  = kt1 + (K2 >> 5);

    float acc[2][8][4];
#pragma unroll
    for (int i = 0; i < 2; i++)
#pragma unroll
        for (int j = 0; j < 8; j++)
#pragma unroll
            for (int q = 0; q < 4; q++) acc[i][j][q] = 0.f;

    auto issue = [&](int kt) {
        const float* A;
        const float* B;
        int K, kk;
        if (kt < kt1) { A = A1; B = B1t; K = K1; kk = kt; }
        else          { A = A2; B = B2t; K = K2; kk = kt - kt1; }
        int s = kt % G_STAGES;
        uint32_t aB = sb + (uint32_t)(s * G_STAGE_BYTES);
        uint32_t bB = aB + G_A_BYTES;
        issue_tile<G_BM>(A, m0, M, K, kk * G_BK, aB, tid);
        issue_tile<G_BN>(B, n0, N, K, kk * G_BK, bB, tid);
    };

    issue(0);
    cp_commit();
    issue(1);
    cp_commit();

    int lrow  = lane & 7;
    int arow0 = wm * 32 + ((lane & 8) ? 8 : 0) + lrow;
    int acol  = (lane & 16) ? 4 : 0;
    uint32_t offA0 = (uint32_t)((arow0)      * G_PAD_STRIDE + acol) * 4;
    uint32_t offA1 = (uint32_t)((arow0 + 16) * G_PAD_STRIDE + acol) * 4;
    int brow0 = wn * 64 + ((lane & 16) ? 8 : 0) + lrow;
    int bcol  = (lane & 8) ? 4 : 0;
    uint32_t offB[4];
#pragma unroll
    for (int tnp = 0; tnp < 4; tnp++)
        offB[tnp] = (uint32_t)((brow0 + tnp * 16) * G_PAD_STRIDE + bcol) * 4;

    int r_lo = (lane >> 2);
    int k_lo = (lane & 3);

    for (int kt = 0; kt < KT; kt++) {
        if (kt + 1 < KT) cp_wait<1>();
        else             cp_wait<0>();
        __syncthreads();

        if (kt + 2 < KT) {
            issue(kt + 2);
            cp_commit();
        }

        int s = kt % G_STAGES;
        uint32_t aBase = sb + (uint32_t)(s * G_STAGE_BYTES);
        uint32_t bBase = aBase + G_A_BYTES;

#pragma unroll
        for (int ks = 0; ks < 4; ks++) {
            uint32_t kb = (uint32_t)(ks * 8 * 4);
            uint32_t af[2][4];
            ldsm_x4(af[0][0], af[0][1], af[0][2], af[0][3], aBase + offA0 + kb);
            ldsm_x4(af[1][0], af[1][1], af[1][2], af[1][3], aBase + offA1 + kb);
            uint32_t bf[8][2];
#pragma unroll
            for (int tnp = 0; tnp < 4; tnp++)
                ldsm_x4(bf[2 * tnp][0], bf[2 * tnp][1],
                        bf[2 * tnp + 1][0], bf[2 * tnp + 1][1],
                        bBase + offB[tnp] + kb);
#pragma unroll
            for (int tm = 0; tm < 2; tm++)
#pragma unroll
                for (int tn = 0; tn < 8; tn++)
                    mma_tf32(acc[tm][tn], af[tm], bf[tn]);
        }
    }

    // epilogue
#pragma unroll
    for (int tm = 0; tm < 2; tm++) {
#pragma unroll
        for (int half = 0; half < 2; half++) {
            int m = m0 + wm * 32 + tm * 16 + half * 8 + r_lo;
            if (m >= M) continue;
#pragma unroll
            for (int tn = 0; tn < 8; tn++) {
                int n = n0 + wn * 64 + tn * 8 + k_lo * 2;
                float2 o;
                o.x = acc[tm][tn][half * 2 + 0];
                o.y = acc[tm][tn][half * 2 + 1];
                if (split_n) {
                    if (n < split_n) {
                        *(float2*)(C + (size_t)m * split_n + n) = o;
                    } else {
                        int n2 = n - split_n;
                        float2 bb = *(const float2*)(bias + n2);
                        o.x += bb.x; o.y += bb.y;
                        *(float2*)(C2 + (size_t)m * split_n + n2) = o;
                    }
                    continue;
                }
                if (bias) {
                    float2 bv = *(const float2*)(bias + n);
                    o.x += bv.x; o.y += bv.y;
                }
                if (relu) {
                    o.x = fmaxf(o.x, 0.f);
                    o.y = fmaxf(o.y, 0.f);
                }
                if (round_out) {
                    o.x = tf32r(o.x);
                    o.y = tf32r(o.y);
                }
                *(float2*)(C + (size_t)m * N + n) = o;
            }
        }
    }
}

// ---------------- launcher -----------------------------------------------------
extern "C" void kernel_launch(void* const* d_in, const int* in_sizes, int n_in,
                              void* d_out, int out_size) {
    const float* x   = (const float*)d_in[0];
    const int*   ei  = (const int*)d_in[1];   // int32 OR int64 (device-detected)
    const float* W1l = (const float*)d_in[2];
    const float* b1  = (const float*)d_in[3];
    const float* W1r = (const float*)d_in[4];
    const float* W2l = (const float*)d_in[5];
    const float* b2  = (const float*)d_in[6];
    const float* W2r = (const float*)d_in[7];
    float* out = (float*)d_out;

    float *xr, *aggA, *h, *p, *q;
    int* cnt;
    float *Wt1l, *Wt1r, *Wt2lr;
    cudaGetSymbolAddress((void**)&cnt,   g_cnt);
    cudaGetSymbolAddress((void**)&xr,    g_xr);
    cudaGetSymbolAddress((void**)&aggA,  g_aggA);
    cudaGetSymbolAddress((void**)&h,     g_h);
    cudaGetSymbolAddress((void**)&p,     g_p);
    cudaGetSymbolAddress((void**)&q,     g_q);
    cudaGetSymbolAddress((void**)&Wt1l,  g_Wt1l);
    cudaGetSymbolAddress((void**)&Wt1r,  g_Wt1r);
    cudaGetSymbolAddress((void**)&Wt2lr, g_Wt2lr);

    static int smem_set = 0;
    if (!smem_set) {
        cudaFuncSetAttribute(gemm_tf32_kernel,
                             cudaFuncAttributeMaxDynamicSharedMemorySize, G_SMEM_SZ);
        smem_set = 1;
    }

    // CSR build: memset node (not a kernel) + 3 kernels
    cudaMemsetAsync(cnt, 0, NN * sizeof(int));
    hist_kernel<<<(EE + 255) / 256, 256>>>(ei);            // kernel 0 (+detect)
    scan_fused<<<SCAN_BLOCKS, 256>>>();                    // kernel 1
    fill_kernel<<<(EE + 255) / 256, 256>>>(ei);            // kernel 2

    // Layer 1 aggregation (+ fused x rounding)             // kernel 3 <- profiled
    agg1_kernel<<<(NN + 7) / 8, 256>>>(x, aggA, xr);

    // Pre-rounded weights
    prep_weights<<<(PREP_TOT + 255) / 256, 256>>>(W1l, W1r, W2l, W2r);

    // Layer 1 GEMM: h = relu(aggA@W1l + xr@W1r + b1), tf32-rounded out
    {
        dim3 grid(FHID / G_BN, (NN + G_BM - 1) / G_BM);
        gemm_tf32_kernel<<<grid, 512, G_SMEM_SZ>>>(
            aggA, Wt1l, FIN, xr, Wt1r, FIN, b1, h, nullptr,
            NN, FHID, 1, 1, 0);
    }
    // Layer 2 fused GEMM: cols 0-255 -> p = h@W2l, cols 256-511 -> q
    {
        dim3 grid((2 * FOUT) / G_BN, (NN + G_BM - 1) / G_BM);
        gemm_tf32_kernel<<<grid, 512, G_SMEM_SZ>>>(
            h, Wt2lr, FHID, nullptr, nullptr, 0, b2, p, q,
            NN, 2 * FOUT, 0, 0, FOUT);
    }
    // out = scatter_mean(p) + q
    agg2_kernel<<<(NN + 7) / 8, 256>>>(p, q, out);
}

// round 14
// speedup vs baseline: 1.3845x; 1.3845x over previous
#include <cuda_runtime.h>
#include <cuda_fp16.h>
#include <cstdint>

// Problem constants (fixed by the dataset generator).
#define NN   40000
#define EE   640000
#define FIN  128
#define FHID 512
#define FOUT 256

#define SCAN_BLOCKS ((NN + 255) / 256)   // 157

// ---------------- scratch (static device globals; no allocation allowed) ----
__device__ int    g_is64;
__device__ int    g_cnt[NN];
__device__ int    g_rowptr[NN + 1];
__device__ int    g_cursor[NN];
__device__ int    g_col[EE];
__device__ __half g_xr  [(size_t)NN * FIN];   // fp16 copy of x           (10 MB)
__device__ __half g_aggA[(size_t)NN * FIN];   // fp16 mean-aggregated x   (10 MB)
__device__ __half g_h   [(size_t)NN * FHID];  // fp16 layer-1 output      (41 MB)
__device__ float  g_p   [(size_t)NN * FOUT];  // h @ W2l                  (40 MB)
__device__ float  g_q   [(size_t)NN * FOUT];  // h @ W2r + b2             (40 MB)
// transposed fp16 weights [N,K]
__device__ __half g_Wt1l[FHID * FIN];
__device__ __half g_Wt1r[FHID * FIN];
__device__ __half g_Wt2lr[2 * FOUT * FHID];   // rows 0-255: W2l^T, 256-511: W2r^T

__device__ __forceinline__ int edge_at(const int* __restrict__ ei, int is64, size_t idx) {
    return is64 ? (int)((const long long*)ei)[idx] : ei[idx];
}

// ---------------- CSR build --------------------------------------------------
__device__ __forceinline__ int detect_is64(const int* __restrict__ ei32) {
    int all0 = 1;
#pragma unroll
    for (int k = 0; k < 64; k++)
        if (__ldg(&ei32[2 * k + 1]) != 0) all0 = 0;
    return all0;
}
__global__ void hist_kernel(const int* __restrict__ ei) {
    __shared__ int s_is64;
    if (threadIdx.x == 0) s_is64 = detect_is64(ei);
    __syncthreads();
    int is64 = s_is64;
    if (blockIdx.x == 0 && threadIdx.x == 0) g_is64 = is64;
    int e = blockIdx.x * blockDim.x + threadIdx.x;
    if (e < EE) atomicAdd(&g_cnt[edge_at(ei, is64, (size_t)EE + e)], 1);
}

__global__ void scan_fused() {
    __shared__ int red[256];
    __shared__ int sh[256];
    int b = blockIdx.x, t = threadIdx.x;

    int lim = b * 256;
    int pre = 0;
    for (int i = t; i < lim; i += 256) pre += g_cnt[i];
    red[t] = pre;
    __syncthreads();
    for (int off = 128; off > 0; off >>= 1) {
        if (t < off) red[t] += red[t + off];
        __syncthreads();
    }
    int blockoff = red[0];

    int i = lim + t;
    int v = (i < NN) ? g_cnt[i] : 0;
    sh[t] = v;
    __syncthreads();
    for (int off = 1; off < 256; off <<= 1) {
        int u = (t >= off) ? sh[t - off] : 0;
        __syncthreads();
        sh[t] += u;
        __syncthreads();
    }
    int excl = sh[t] - v + blockoff;
    if (i < NN) {
        g_rowptr[i] = excl;
        g_cursor[i] = excl;
    }
    if (b == 0 && t == 0) g_rowptr[NN] = EE;
}

__global__ void fill_kernel(const int* __restrict__ ei) {
    int e = blockIdx.x * blockDim.x + threadIdx.x;
    if (e < EE) {
        int is64 = g_is64;
        int d = edge_at(ei, is64, (size_t)EE + e);
        int s = edge_at(ei, is64, (size_t)e);
        int pos = atomicAdd(&g_cursor[d], 1);
        g_col[pos] = s;
    }
}

// ---------------- fused weight prep: transpose + fp16 convert -----------------
#define W1_ELEMS (FIN * FHID)
#define W2_ELEMS (FHID * FOUT)
__global__ void prep_weights(const float* __restrict__ W1l, const float* __restrict__ W1r,
                             const float* __restrict__ W2l, const float* __restrict__ W2r) {
    int idx = blockIdx.x * blockDim.x + threadIdx.x;
    if (idx < W1_ELEMS) {
        int k = idx / FHID, n = idx % FHID;
        g_Wt1l[(size_t)n * FIN + k] = __float2half_rn(W1l[idx]);
        return;
    }
    idx -= W1_ELEMS;
    if (idx < W1_ELEMS) {
        int k = idx / FHID, n = idx % FHID;
        g_Wt1r[(size_t)n * FIN + k] = __float2half_rn(W1r[idx]);
        return;
    }
    idx -= W1_ELEMS;
    if (idx < W2_ELEMS) {
        int k = idx / FOUT, n = idx % FOUT;
        g_Wt2lr[(size_t)n * FHID + k] = __float2half_rn(W2l[idx]);
        return;
    }
    idx -= W2_ELEMS;
    if (idx < W2_ELEMS) {
        int k = idx / FOUT, n = idx % FOUT;
        g_Wt2lr[(size_t)(n + FOUT) * FHID + k] = __float2half_rn(W2r[idx]);
    }
}
#define PREP_TOT (2 * W1_ELEMS + 2 * W2_ELEMS)

// ---------------- layer-1 aggregation (warp per node, fp32 gather, fp16 out) --
__global__ void __launch_bounds__(256)
agg1_kernel(const float* __restrict__ x, __half* __restrict__ aggA,
            __half* __restrict__ xr) {
    int node = blockIdx.x * (blockDim.x >> 5) + (threadIdx.x >> 5);
    if (node >= NN) return;
    int lane = threadIdx.x & 31;
    int beg = g_rowptr[node];
    int end = g_rowptr[node + 1];

    const float4* fb = (const float4*)x;   // row = 32 float4
    float4 acc = make_float4(0.f, 0.f, 0.f, 0.f);

    int j = beg;
    for (; j + 3 < end; j += 4) {
        int s0 = __ldg(&g_col[j + 0]);
        int s1 = __ldg(&g_col[j + 1]);
        int s2 = __ldg(&g_col[j + 2]);
        int s3 = __ldg(&g_col[j + 3]);
        float4 a0 = fb[(size_t)s0 * 32 + lane];
        float4 a1 = fb[(size_t)s1 * 32 + lane];
        float4 a2 = fb[(size_t)s2 * 32 + lane];
        float4 a3 = fb[(size_t)s3 * 32 + lane];
        acc.x += (a0.x + a1.x) + (a2.x + a3.x);
        acc.y += (a0.y + a1.y) + (a2.y + a3.y);
        acc.z += (a0.z + a1.z) + (a2.z + a3.z);
        acc.w += (a0.w + a1.w) + (a2.w + a3.w);
    }
    for (; j < end; j++) {
        int s0 = __ldg(&g_col[j]);
        float4 a = fb[(size_t)s0 * 32 + lane];
        acc.x += a.x; acc.y += a.y; acc.z += a.z; acc.w += a.w;
    }
    float inv = 1.0f / (float)max(end - beg, 1);
    __half2* arow = (__half2*)(aggA + (size_t)node * FIN);
    arow[lane * 2 + 0] = __floats2half2_rn(acc.x * inv, acc.y * inv);
    arow[lane * 2 + 1] = __floats2half2_rn(acc.z * inv, acc.w * inv);

    float4 v = fb[(size_t)node * 32 + lane];
    __half2* xrow = (__half2*)(xr + (size_t)node * FIN);
    xrow[lane * 2 + 0] = __floats2half2_rn(v.x, v.y);
    xrow[lane * 2 + 1] = __floats2half2_rn(v.z, v.w);
}

// ---------------- layer-2 aggregation (warp per node, fp32, +q residual) ------
__global__ void __launch_bounds__(256)
agg2_kernel(const float* __restrict__ p, const float* __restrict__ q,
            float* __restrict__ out) {
    int node = blockIdx.x * (blockDim.x >> 5) + (threadIdx.x >> 5);
    if (node >= NN) return;
    int lane = threadIdx.x & 31;
    int beg = g_rowptr[node];
    int end = g_rowptr[node + 1];

    const float4* fb = (const float4*)p;   // row = 64 float4
    float4 acc0 = make_float4(0.f, 0.f, 0.f, 0.f);
    float4 acc1 = make_float4(0.f, 0.f, 0.f, 0.f);

    int j = beg;
    for (; j + 3 < end; j += 4) {
        int s0 = __ldg(&g_col[j + 0]);
        int s1 = __ldg(&g_col[j + 1]);
        int s2 = __ldg(&g_col[j + 2]);
        int s3 = __ldg(&g_col[j + 3]);
        const float4* r0 = fb + (size_t)s0 * 64;
        const float4* r1 = fb + (size_t)s1 * 64;
        const float4* r2 = fb + (size_t)s2 * 64;
        const float4* r3 = fb + (size_t)s3 * 64;
        float4 a0 = r0[lane],      b0 = r1[lane],      c0 = r2[lane],      d0 = r3[lane];
        float4 a1 = r0[lane + 32], b1 = r1[lane + 32], c1 = r2[lane + 32], d1 = r3[lane + 32];
        acc0.x += (a0.x + b0.x) + (c0.x + d0.x);
        acc0.y += (a0.y + b0.y) + (c0.y + d0.y);
        acc0.z += (a0.z + b0.z) + (c0.z + d0.z);
        acc0.w += (a0.w + b0.w) + (c0.w + d0.w);
        acc1.x += (a1.x + b1.x) + (c1.x + d1.x);
        acc1.y += (a1.y + b1.y) + (c1.y + d1.y);
        acc1.z += (a1.z + b1.z) + (c1.z + d1.z);
        acc1.w += (a1.w + b1.w) + (c1.w + d1.w);
    }
    for (; j < end; j++) {
        int s0 = __ldg(&g_col[j]);
        const float4* r0 = fb + (size_t)s0 * 64;
        float4 a0 = r0[lane], a1 = r0[lane + 32];
        acc0.x += a0.x; acc0.y += a0.y; acc0.z += a0.z; acc0.w += a0.w;
        acc1.x += a1.x; acc1.y += a1.y; acc1.z += a1.z; acc1.w += a1.w;
    }
    float inv = 1.0f / (float)max(end - beg, 1);
    const float4* qv = (const float4*)(q + (size_t)node * FOUT);
    float4* ov = (float4*)(out + (size_t)node * FOUT);
    float4 q0 = qv[lane], q1 = qv[lane + 32];
    float4 o0, o1;
    o0.x = acc0.x * inv + q0.x; o0.y = acc0.y * inv + q0.y;
    o0.z = acc0.z * inv + q0.z; o0.w = acc0.w * inv + q0.w;
    o1.x = acc1.x * inv + q1.x; o1.y = acc1.y * inv + q1.y;
    o1.z = acc1.z * inv + q1.z; o1.w = acc1.w * inv + q1.w;
    ov[lane]      = o0;
    ov[lane + 32] = o1;
}

// ================= fp16 mma.sync m16n8k16 GEMM, BM=128 x BN=256, 3-stage =====
// fp16 operands carry 10 explicit mantissa bits (same as tf32); fp32 accum.
// BK = 64 halves = 128B rows, padded to 144B (16B-aligned, ldmatrix
// conflict-free: phase 9i mod 8 covers all banks).
#define G_BM 128
#define G_BN 256
#define G_BK 64                                // halves per k-tile
#define G_STAGES 3
#define G_STRIDE_H 72                          // halves per smem row (144 B)
#define G_A_BYTES (G_BM * G_STRIDE_H * 2)      // 18432
#define G_B_BYTES (G_BN * G_STRIDE_H * 2)      // 36864
#define G_STAGE_BYTES (G_A_BYTES + G_B_BYTES)  // 55296
#define G_SMEM_SZ (G_STAGES * G_STAGE_BYTES)   // 165888

__device__ __forceinline__ uint32_t smem_u32(const void* p) {
    uint32_t a;
    asm("{ .reg .u64 t; cvta.to.shared.u64 t, %1; cvt.u32.u64 %0, t; }"
        : "=r"(a) : "l"(p));
    return a;
}
__device__ __forceinline__ void cp_async16(uint32_t dst, const void* src, int src_bytes) {
    asm volatile("cp.async.ca.shared.global [%0], [%1], 16, %2;"
                 :: "r"(dst), "l"(src), "r"(src_bytes) : "memory");
}
__device__ __forceinline__ void cp_commit() {
    asm volatile("cp.async.commit_group;" ::: "memory");
}
template <int NPEND>
__device__ __forceinline__ void cp_wait() {
    asm volatile("cp.async.wait_group %0;" :: "n"(NPEND) : "memory");
}
__device__ __forceinline__ void mma_f16(float* d, const uint32_t* a, const uint32_t* b) {
    asm volatile(
        "mma.sync.aligned.m16n8k16.row.col.f32.f16.f16.f32 "
        "{%0,%1,%2,%3}, {%4,%5,%6,%7}, {%8,%9}, {%0,%1,%2,%3};"
        : "+f"(d[0]), "+f"(d[1]), "+f"(d[2]), "+f"(d[3])
        : "r"(a[0]), "r"(a[1]), "r"(a[2]), "r"(a[3]), "r"(b[0]), "r"(b[1]));
}
__device__ __forceinline__ void ldsm_x4(uint32_t& d0, uint32_t& d1, uint32_t& d2,
                                        uint32_t& d3, uint32_t addr) {
    asm volatile("ldmatrix.sync.aligned.m8n8.x4.shared.b16 {%0,%1,%2,%3}, [%4];"
                 : "=r"(d0), "=r"(d1), "=r"(d2), "=r"(d3) : "r"(addr));
}

// ROWS x 64-half tile (128B/row) -> smem via cp.async (512 threads).
template <int ROWS>
__device__ __forceinline__ void issue_tile(
    const __half* __restrict__ src, int row0, int row_lim, int K, int k0,
    uint32_t dst_base, int tid) {
#pragma unroll
    for (int u = 0; u < (ROWS * 8) / 512; u++) {
        int id  = u * 512 + tid;
        int row = id >> 3;
        int c   = id & 7;                      // 16B chunk = 8 halves
        int gr  = row0 + row;
        int ok  = gr < row_lim;
        const __half* s = src + (size_t)(ok ? gr : (row_lim - 1)) * K + k0 + c * 8;
        cp_async16(dst_base + row * (G_STRIDE_H * 2) + c * 16, s, ok ? 16 : 0);
    }
}

// split_n == 0: fp32 C (+bias/relu) or fp16 Ch (half_out).
// split_n  > 0: cols < split_n -> C (fp32, no bias), cols >= split_n -> C2 (+bias).
__global__ void __launch_bounds__(512, 1)
gemm_fp16_kernel(const __half* __restrict__ A1, const __half* __restrict__ B1t, int K1,
                 const __half* __restrict__ A2, const __half* __restrict__ B2t, int K2,
                 const float* __restrict__ bias,
                 float* __restrict__ C, __half* __restrict__ Ch,
                 float* __restrict__ C2,
                 int M, int N, int relu, int half_out, int split_n) {
    extern __shared__ char smem[];
    uint32_t sb = smem_u32(smem);

    int tid  = threadIdx.x;
    int lane = tid & 31;
    int wid  = tid >> 5;
    int wm   = wid & 3;         // 4 x 32 = 128 rows
    int wn   = wid >> 2;        // 4 x 64 = 256 cols
    int m0 = blockIdx.y * G_BM;
    int n0 = blockIdx.x * G_BN;

    const int kt1 = K1 / G_BK;
    const int KT  = kt1 + K2 / G_BK;

    float acc[2][8][4];
#pragma unroll
    for (int i = 0; i < 2; i++)
#pragma unroll
        for (int j = 0; j < 8; j++)
#pragma unroll
            for (int q = 0; q < 4; q++) acc[i][j][q] = 0.f;

    auto issue = [&](int kt) {
        const __half* A;
        const __half* B;
        int K, kk;
        if (kt < kt1) { A = A1; B = B1t; K = K1; kk = kt; }
        else          { A = A2; B = B2t; K = K2; kk = kt - kt1; }
        int s = kt % G_STAGES;
        uint32_t aB = sb + (uint32_t)(s * G_STAGE_BYTES);
        uint32_t bB = aB + G_A_BYTES;
        issue_tile<G_BM>(A, m0, M, K, kk * G_BK, aB, tid);
        issue_tile<G_BN>(B, n0, N, K, kk * G_BK, bB, tid);
    };

    issue(0);
    cp_commit();
    issue(1);
    cp_commit();

    // ldmatrix per-lane byte offsets within a stage.
    // A x4 (per tm): matrices (r..r+7,k0-7),(r+8..r+15,k0-7),(r..,k8-15),(r+8..,k8-15)
    int lrow = lane & 7;
    int arow = wm * 32 + ((lane & 8) ? 8 : 0) + lrow;        // + tm*16
    int acol = (lane & 16) ? 8 : 0;                          // halves
    uint32_t offA0 = (uint32_t)(arow * G_STRIDE_H + acol) * 2;
    uint32_t offA1 = (uint32_t)((arow + 16) * G_STRIDE_H + acol) * 2;
    // B x4 (per tn pair): (n..n+7,k0-7),(n..n+7,k8-15),(n+8..,k0-7),(n+8..,k8-15)
    int brow = wn * 64 + ((lane & 16) ? 8 : 0) + lrow;       // + tnp*16
    int bcol = (lane & 8) ? 8 : 0;                           // halves
    uint32_t offB[4];
#pragma unroll
    for (int tnp = 0; tnp < 4; tnp++)
        offB[tnp] = (uint32_t)((brow + tnp * 16) * G_STRIDE_H + bcol) * 2;

    int r_lo = (lane >> 2);
    int k_lo = (lane & 3);

    for (int kt = 0; kt < KT; kt++) {
        if (kt + 1 < KT) cp_wait<1>();
        else             cp_wait<0>();
        __syncthreads();

        if (kt + 2 < KT) {
            issue(kt + 2);
            cp_commit();
        }

        int s = kt % G_STAGES;
        uint32_t aBase = sb + (uint32_t)(s * G_STAGE_BYTES);
        uint32_t bBase = aBase + G_A_BYTES;

#pragma unroll
        for (int ks = 0; ks < 4; ks++) {           // 4 x k16 = 64 halves
            uint32_t kb = (uint32_t)(ks * 16 * 2); // bytes
            uint32_t af[2][4];
            ldsm_x4(af[0][0], af[0][1], af[0][2], af[0][3], aBase + offA0 + kb);
            ldsm_x4(af[1][0], af[1][1], af[1][2], af[1][3], aBase + offA1 + kb);
            uint32_t bf[8][2];
#pragma unroll
            for (int tnp = 0; tnp < 4; tnp++)
                ldsm_x4(bf[2 * tnp][0], bf[2 * tnp][1],
                        bf[2 * tnp + 1][0], bf[2 * tnp + 1][1],
                        bBase + offB[tnp] + kb);
#pragma unroll
            for (int tm = 0; tm < 2; tm++)
#pragma unroll
                for (int tn = 0; tn < 8; tn++)
                    mma_f16(acc[tm][tn], af[tm], bf[tn]);
        }
    }

    // epilogue (same c-fragment layout as m16n8k8: lane -> (l/4, 2*(l%4)))
#pragma unroll
    for (int tm = 0; tm < 2; tm++) {
#pragma unroll
        for (int half = 0; half < 2; half++) {
            int m = m0 + wm * 32 + tm * 16 + half * 8 + r_lo;
            if (m >= M) continue;
#pragma unroll
            for (int tn = 0; tn < 8; tn++) {
                int n = n0 + wn * 64 + tn * 8 + k_lo * 2;
                float2 o;
                o.x = acc[tm][tn][half * 2 + 0];
                o.y = acc[tm][tn][half * 2 + 1];
                if (split_n) {
                    if (n < split_n) {
                        *(float2*)(C + (size_t)m * split_n + n) = o;
                    } else {
                        int n2 = n - split_n;
                        float2 bb = *(const float2*)(bias + n2);
                        o.x += bb.x; o.y += bb.y;
                        *(float2*)(C2 + (size_t)m * split_n + n2) = o;
                    }
                    continue;
                }
                if (bias) {
                    float2 bv = *(const float2*)(bias + n);
                    o.x += bv.x; o.y += bv.y;
                }
                if (relu) {
                    o.x = fmaxf(o.x, 0.f);
                    o.y = fmaxf(o.y, 0.f);
                }
                if (half_out) {
                    *(__half2*)(Ch + (size_t)m * N + n) = __floats2half2_rn(o.x, o.y);
                } else {
                    *(float2*)(C + (size_t)m * N + n) = o;
                }
            }
        }
    }
}

// ---------------- launcher -----------------------------------------------------
extern "C" void kernel_launch(void* const* d_in, const int* in_sizes, int n_in,
                              void* d_out, int out_size) {
    const float* x   = (const float*)d_in[0];
    const int*   ei  = (const int*)d_in[1];   // int32 OR int64 (device-detected)
    const float* W1l = (const float*)d_in[2];
    const float* b1  = (const float*)d_in[3];
    const float* W1r = (const float*)d_in[4];
    const float* W2l = (const float*)d_in[5];
    const float* b2  = (const float*)d_in[6];
    const float* W2r = (const float*)d_in[7];
    float* out = (float*)d_out;

    int* cnt;
    __half *xr, *aggA, *h, *Wt1l, *Wt1r, *Wt2lr;
    float *p, *q;
    cudaGetSymbolAddress((void**)&cnt,   g_cnt);
    cudaGetSymbolAddress((void**)&xr,    g_xr);
    cudaGetSymbolAddress((void**)&aggA,  g_aggA);
    cudaGetSymbolAddress((void**)&h,     g_h);
    cudaGetSymbolAddress((void**)&p,     g_p);
    cudaGetSymbolAddress((void**)&q,     g_q);
    cudaGetSymbolAddress((void**)&Wt1l,  g_Wt1l);
    cudaGetSymbolAddress((void**)&Wt1r,  g_Wt1r);
    cudaGetSymbolAddress((void**)&Wt2lr, g_Wt2lr);

    static int smem_set = 0;
    if (!smem_set) {
        cudaFuncSetAttribute(gemm_fp16_kernel,
                             cudaFuncAttributeMaxDynamicSharedMemorySize, G_SMEM_SZ);
        smem_set = 1;
    }

    // CSR build: memset node + 3 kernels
    cudaMemsetAsync(cnt, 0, NN * sizeof(int));
    hist_kernel<<<(EE + 255) / 256, 256>>>(ei);
    scan_fused<<<SCAN_BLOCKS, 256>>>();
    fill_kernel<<<(EE + 255) / 256, 256>>>(ei);

    // Layer 1 aggregation (+ fused fp16 conversion of x)
    agg1_kernel<<<(NN + 7) / 8, 256>>>(x, aggA, xr);

    // fp16 weights
    prep_weights<<<(PREP_TOT + 255) / 256, 256>>>(W1l, W1r, W2l, W2r);

    // Layer 1 GEMM: h = relu(aggA@W1l + xr@W1r + b1), fp16 out
    {
        dim3 grid(FHID / G_BN, (NN + G_BM - 1) / G_BM);
        gemm_fp16_kernel<<<grid, 512, G_SMEM_SZ>>>(
            aggA, Wt1l, FIN, xr, Wt1r, FIN, b1, nullptr, h, nullptr,
            NN, FHID, 1, 1, 0);
    }
    // Layer 2 fused GEMM: cols 0-255 -> p = h@W2l, cols 256-511 -> q = h@W2r + b2
    {
        dim3 grid((2 * FOUT) / G_BN, (NN + G_BM - 1) / G_BM);
        gemm_fp16_kernel<<<grid, 512, G_SMEM_SZ>>>(
            h, Wt2lr, FHID, nullptr, nullptr, 0, b2, p, nullptr, q,
            NN, 2 * FOUT, 0, 0, FOUT);
    }
    // out = scatter_mean(p) + q
    agg2_kernel<<<(NN + 7) / 8, 256>>>(p, q, out);
}

// round 15
// speedup vs baseline: 1.4942x; 1.0792x over previous
#include <cuda_runtime.h>
#include <cuda_fp16.h>
#include <cstdint>

// Problem constants (fixed by the dataset generator).
#define NN   40000
#define EE   640000
#define FIN  128
#define FHID 512
#define FOUT 256

#define SCAN_BLOCKS ((NN + 255) / 256)   // 157

// ---------------- scratch (static device globals; no allocation allowed) ----
__device__ int    g_is64;
__device__ int    g_cnt[NN];
__device__ int    g_rowptr[NN + 1];
__device__ int    g_cursor[NN];
__device__ int    g_col[EE];
__device__ __half g_xr  [(size_t)NN * FIN];   // fp16 copy of x           (10 MB)
__device__ __half g_aggA[(size_t)NN * FIN];   // fp16 mean-aggregated x   (10 MB)
__device__ __half g_h   [(size_t)NN * FHID];  // fp16 layer-1 output      (41 MB)
__device__ __half g_p   [(size_t)NN * FOUT];  // h @ W2l, fp16            (20 MB)
__device__ float  g_q   [(size_t)NN * FOUT];  // h @ W2r + b2             (40 MB)
// transposed fp16 weights [N,K]
__device__ __half g_Wt1l[FHID * FIN];
__device__ __half g_Wt1r[FHID * FIN];
__device__ __half g_Wt2lr[2 * FOUT * FHID];   // rows 0-255: W2l^T, 256-511: W2r^T

__device__ __forceinline__ int edge_at(const int* __restrict__ ei, int is64, size_t idx) {
    return is64 ? (int)((const long long*)ei)[idx] : ei[idx];
}

// ---------------- CSR build --------------------------------------------------
__device__ __forceinline__ int detect_is64(const int* __restrict__ ei32) {
    int all0 = 1;
#pragma unroll
    for (int k = 0; k < 64; k++)
        if (__ldg(&ei32[2 * k + 1]) != 0) all0 = 0;
    return all0;
}
__global__ void hist_kernel(const int* __restrict__ ei) {
    __shared__ int s_is64;
    if (threadIdx.x == 0) s_is64 = detect_is64(ei);
    __syncthreads();
    int is64 = s_is64;
    if (blockIdx.x == 0 && threadIdx.x == 0) g_is64 = is64;
    int e = blockIdx.x * blockDim.x + threadIdx.x;
    if (e < EE) atomicAdd(&g_cnt[edge_at(ei, is64, (size_t)EE + e)], 1);
}

__global__ void scan_fused() {
    __shared__ int red[256];
    __shared__ int sh[256];
    int b = blockIdx.x, t = threadIdx.x;

    int lim = b * 256;
    int pre = 0;
    for (int i = t; i < lim; i += 256) pre += g_cnt[i];
    red[t] = pre;
    __syncthreads();
    for (int off = 128; off > 0; off >>= 1) {
        if (t < off) red[t] += red[t + off];
        __syncthreads();
    }
    int blockoff = red[0];

    int i = lim + t;
    int v = (i < NN) ? g_cnt[i] : 0;
    sh[t] = v;
    __syncthreads();
    for (int off = 1; off < 256; off <<= 1) {
        int u = (t >= off) ? sh[t - off] : 0;
        __syncthreads();
        sh[t] += u;
        __syncthreads();
    }
    int excl = sh[t] - v + blockoff;
    if (i < NN) {
        g_rowptr[i] = excl;
        g_cursor[i] = excl;
    }
    if (b == 0 && t == 0) g_rowptr[NN] = EE;
}

__global__ void fill_kernel(const int* __restrict__ ei) {
    int e = blockIdx.x * blockDim.x + threadIdx.x;
    if (e < EE) {
        int is64 = g_is64;
        int d = edge_at(ei, is64, (size_t)EE + e);
        int s = edge_at(ei, is64, (size_t)e);
        int pos = atomicAdd(&g_cursor[d], 1);
        g_col[pos] = s;
    }
}

// ---------------- fused weight prep: transpose + fp16 convert -----------------
#define W1_ELEMS (FIN * FHID)
#define W2_ELEMS (FHID * FOUT)
__global__ void prep_weights(const float* __restrict__ W1l, const float* __restrict__ W1r,
                             const float* __restrict__ W2l, const float* __restrict__ W2r) {
    int idx = blockIdx.x * blockDim.x + threadIdx.x;
    if (idx < W1_ELEMS) {
        int k = idx / FHID, n = idx % FHID;
        g_Wt1l[(size_t)n * FIN + k] = __float2half_rn(W1l[idx]);
        return;
    }
    idx -= W1_ELEMS;
    if (idx < W1_ELEMS) {
        int k = idx / FHID, n = idx % FHID;
        g_Wt1r[(size_t)n * FIN + k] = __float2half_rn(W1r[idx]);
        return;
    }
    idx -= W1_ELEMS;
    if (idx < W2_ELEMS) {
        int k = idx / FOUT, n = idx % FOUT;
        g_Wt2lr[(size_t)n * FHID + k] = __float2half_rn(W2l[idx]);
        return;
    }
    idx -= W2_ELEMS;
    if (idx < W2_ELEMS) {
        int k = idx / FOUT, n = idx % FOUT;
        g_Wt2lr[(size_t)(n + FOUT) * FHID + k] = __float2half_rn(W2r[idx]);
    }
}
#define PREP_TOT (2 * W1_ELEMS + 2 * W2_ELEMS)

// ---------------- layer-1 aggregation (warp per node, fp32 gather, fp16 out) --
__global__ void __launch_bounds__(256)
agg1_kernel(const float* __restrict__ x, __half* __restrict__ aggA,
            __half* __restrict__ xr) {
    int node = blockIdx.x * (blockDim.x >> 5) + (threadIdx.x >> 5);
    if (node >= NN) return;
    int lane = threadIdx.x & 31;
    int beg = g_rowptr[node];
    int end = g_rowptr[node + 1];

    const float4* fb = (const float4*)x;   // row = 32 float4
    float4 acc = make_float4(0.f, 0.f, 0.f, 0.f);

    int j = beg;
    for (; j + 3 < end; j += 4) {
        int s0 = __ldg(&g_col[j + 0]);
        int s1 = __ldg(&g_col[j + 1]);
        int s2 = __ldg(&g_col[j + 2]);
        int s3 = __ldg(&g_col[j + 3]);
        float4 a0 = fb[(size_t)s0 * 32 + lane];
        float4 a1 = fb[(size_t)s1 * 32 + lane];
        float4 a2 = fb[(size_t)s2 * 32 + lane];
        float4 a3 = fb[(size_t)s3 * 32 + lane];
        acc.x += (a0.x + a1.x) + (a2.x + a3.x);
        acc.y += (a0.y + a1.y) + (a2.y + a3.y);
        acc.z += (a0.z + a1.z) + (a2.z + a3.z);
        acc.w += (a0.w + a1.w) + (a2.w + a3.w);
    }
    for (; j < end; j++) {
        int s0 = __ldg(&g_col[j]);
        float4 a = fb[(size_t)s0 * 32 + lane];
        acc.x += a.x; acc.y += a.y; acc.z += a.z; acc.w += a.w;
    }
    float inv = 1.0f / (float)max(end - beg, 1);
    __half2* arow = (__half2*)(aggA + (size_t)node * FIN);
    arow[lane * 2 + 0] = __floats2half2_rn(acc.x * inv, acc.y * inv);
    arow[lane * 2 + 1] = __floats2half2_rn(acc.z * inv, acc.w * inv);

    float4 v = fb[(size_t)node * 32 + lane];
    __half2* xrow = (__half2*)(xr + (size_t)node * FIN);
    xrow[lane * 2 + 0] = __floats2half2_rn(v.x, v.y);
    xrow[lane * 2 + 1] = __floats2half2_rn(v.z, v.w);
}

// ---------------- layer-2 aggregation (warp per node, fp16 gather, +q) --------
// Row of p = 256 halves = 512 B = 32 uint4; lane owns one uint4 (8 halves).
// Accumulation in fp32; out = mean + q (q fp32).
__global__ void __launch_bounds__(256)
agg2_kernel(const __half* __restrict__ p, const float* __restrict__ q,
            float* __restrict__ out) {
    int node = blockIdx.x * (blockDim.x >> 5) + (threadIdx.x >> 5);
    if (node >= NN) return;
    int lane = threadIdx.x & 31;
    int beg = g_rowptr[node];
    int end = g_rowptr[node + 1];

    const uint4* fb = (const uint4*)p;   // row = 32 uint4
    float acc[8];
#pragma unroll
    for (int i = 0; i < 8; i++) acc[i] = 0.f;

    auto accum = [&](uint4 u) {
        float2 f0 = __half22float2(*(const __half2*)&u.x);
        float2 f1 = __half22float2(*(const __half2*)&u.y);
        float2 f2 = __half22float2(*(const __half2*)&u.z);
        float2 f3 = __half22float2(*(const __half2*)&u.w);
        acc[0] += f0.x; acc[1] += f0.y;
        acc[2] += f1.x; acc[3] += f1.y;
        acc[4] += f2.x; acc[5] += f2.y;
        acc[6] += f3.x; acc[7] += f3.y;
    };

    int j = beg;
    for (; j + 3 < end; j += 4) {
        int s0 = __ldg(&g_col[j + 0]);
        int s1 = __ldg(&g_col[j + 1]);
        int s2 = __ldg(&g_col[j + 2]);
        int s3 = __ldg(&g_col[j + 3]);
        uint4 u0 = fb[(size_t)s0 * 32 + lane];
        uint4 u1 = fb[(size_t)s1 * 32 + lane];
        uint4 u2 = fb[(size_t)s2 * 32 + lane];
        uint4 u3 = fb[(size_t)s3 * 32 + lane];
        accum(u0); accum(u1); accum(u2); accum(u3);
    }
    for (; j < end; j++) {
        int s0 = __ldg(&g_col[j]);
        accum(fb[(size_t)s0 * 32 + lane]);
    }

    float inv = 1.0f / (float)max(end - beg, 1);
    // q/out rows: 64 float4; lane owns float4 indices 2*lane, 2*lane+1
    const float4* qv = (const float4*)(q + (size_t)node * FOUT);
    float4* ov = (float4*)(out + (size_t)node * FOUT);
    float4 q0 = qv[2 * lane], q1 = qv[2 * lane + 1];
    float4 o0, o1;
    o0.x = acc[0] * inv + q0.x; o0.y = acc[1] * inv + q0.y;
    o0.z = acc[2] * inv + q0.z; o0.w = acc[3] * inv + q0.w;
    o1.x = acc[4] * inv + q1.x; o1.y = acc[5] * inv + q1.y;
    o1.z = acc[6] * inv + q1.z; o1.w = acc[7] * inv + q1.w;
    ov[2 * lane]     = o0;
    ov[2 * lane + 1] = o1;
}

// ================= fp16 mma.sync m16n8k16 GEMM, BM=128 x BN=256, 3-stage =====
#define G_BM 128
#define G_BN 256
#define G_BK 64                                // halves per k-tile
#define G_STAGES 3
#define G_STRIDE_H 72                          // halves per smem row (144 B)
#define G_A_BYTES (G_BM * G_STRIDE_H * 2)      // 18432
#define G_B_BYTES (G_BN * G_STRIDE_H * 2)      // 36864
#define G_STAGE_BYTES (G_A_BYTES + G_B_BYTES)  // 55296
#define G_SMEM_SZ (G_STAGES * G_STAGE_BYTES)   // 165888

__device__ __forceinline__ uint32_t smem_u32(const void* p) {
    uint32_t a;
    asm("{ .reg .u64 t; cvta.to.shared.u64 t, %1; cvt.u32.u64 %0, t; }"
        : "=r"(a) : "l"(p));
    return a;
}
__device__ __forceinline__ void cp_async16(uint32_t dst, const void* src, int src_bytes) {
    asm volatile("cp.async.ca.shared.global [%0], [%1], 16, %2;"
                 :: "r"(dst), "l"(src), "r"(src_bytes) : "memory");
}
__device__ __forceinline__ void cp_commit() {
    asm volatile("cp.async.commit_group;" ::: "memory");
}
template <int NPEND>
__device__ __forceinline__ void cp_wait() {
    asm volatile("cp.async.wait_group %0;" :: "n"(NPEND) : "memory");
}
__device__ __forceinline__ void mma_f16(float* d, const uint32_t* a, const uint32_t* b) {
    asm volatile(
        "mma.sync.aligned.m16n8k16.row.col.f32.f16.f16.f32 "
        "{%0,%1,%2,%3}, {%4,%5,%6,%7}, {%8,%9}, {%0,%1,%2,%3};"
        : "+f"(d[0]), "+f"(d[1]), "+f"(d[2]), "+f"(d[3])
        : "r"(a[0]), "r"(a[1]), "r"(a[2]), "r"(a[3]), "r"(b[0]), "r"(b[1]));
}
__device__ __forceinline__ void ldsm_x4(uint32_t& d0, uint32_t& d1, uint32_t& d2,
                                        uint32_t& d3, uint32_t addr) {
    asm volatile("ldmatrix.sync.aligned.m8n8.x4.shared.b16 {%0,%1,%2,%3}, [%4];"
                 : "=r"(d0), "=r"(d1), "=r"(d2), "=r"(d3) : "r"(addr));
}

template <int ROWS>
__device__ __forceinline__ void issue_tile(
    const __half* __restrict__ src, int row0, int row_lim, int K, int k0,
    uint32_t dst_base, int tid) {
#pragma unroll
    for (int u = 0; u < (ROWS * 8) / 512; u++) {
        int id  = u * 512 + tid;
        int row = id >> 3;
        int c   = id & 7;
        int gr  = row0 + row;
        int ok  = gr < row_lim;
        const __half* s = src + (size_t)(ok ? gr : (row_lim - 1)) * K + k0 + c * 8;
        cp_async16(dst_base + row * (G_STRIDE_H * 2) + c * 16, s, ok ? 16 : 0);
    }
}

// split_n == 0: fp32 C (+bias/relu) or fp16 Ch (half_out).
// split_n  > 0: cols < split_n -> Cph (fp16, no bias), cols >= split_n -> C2 (+bias).
__global__ void __launch_bounds__(512, 1)
gemm_fp16_kernel(const __half* __restrict__ A1, const __half* __restrict__ B1t, int K1,
                 const __half* __restrict__ A2, const __half* __restrict__ B2t, int K2,
                 const float* __restrict__ bias,
                 float* __restrict__ C, __half* __restrict__ Ch,
                 __half* __restrict__ Cph, float* __restrict__ C2,
                 int M, int N, int relu, int half_out, int split_n) {
    extern __shared__ char smem[];
    uint32_t sb = smem_u32(smem);

    int tid  = threadIdx.x;
    int lane = tid & 31;
    int wid  = tid >> 5;
    int wm   = wid & 3;
    int wn   = wid >> 2;
    int m0 = blockIdx.y * G_BM;
    int n0 = blockIdx.x * G_BN;

    const int kt1 = K1 / G_BK;
    const int KT  = kt1 + K2 / G_BK;

    float acc[2][8][4];
#pragma unroll
    for (int i = 0; i < 2; i++)
#pragma unroll
        for (int j = 0; j < 8; j++)
#pragma unroll
            for (int q = 0; q < 4; q++) acc[i][j][q] = 0.f;

    auto issue = [&](int kt) {
        const __half* A;
        const __half* B;
        int K, kk;
        if (kt < kt1) { A = A1; B = B1t; K = K1; kk = kt; }
        else          { A = A2; B = B2t; K = K2; kk = kt - kt1; }
        int s = kt % G_STAGES;
        uint32_t aB = sb + (uint32_t)(s * G_STAGE_BYTES);
        uint32_t bB = aB + G_A_BYTES;
        issue_tile<G_BM>(A, m0, M, K, kk * G_BK, aB, tid);
        issue_tile<G_BN>(B, n0, N, K, kk * G_BK, bB, tid);
    };

    issue(0);
    cp_commit();
    issue(1);
    cp_commit();

    int lrow = lane & 7;
    int arow = wm * 32 + ((lane & 8) ? 8 : 0) + lrow;
    int acol = (lane & 16) ? 8 : 0;
    uint32_t offA0 = (uint32_t)(arow * G_STRIDE_H + acol) * 2;
    uint32_t offA1 = (uint32_t)((arow + 16) * G_STRIDE_H + acol) * 2;
    int brow = wn * 64 + ((lane & 16) ? 8 : 0) + lrow;
    int bcol = (lane & 8) ? 8 : 0;
    uint32_t offB[4];
#pragma unroll
    for (int tnp = 0; tnp < 4; tnp++)
        offB[tnp] = (uint32_t)((brow + tnp * 16) * G_STRIDE_H + bcol) * 2;

    int r_lo = (lane >> 2);
    int k_lo = (lane & 3);

    for (int kt = 0; kt < KT; kt++) {
        if (kt + 1 < KT) cp_wait<1>();
        else             cp_wait<0>();
        __syncthreads();

        if (kt + 2 < KT) {
            issue(kt + 2);
            cp_commit();
        }

        int s = kt % G_STAGES;
        uint32_t aBase = sb + (uint32_t)(s * G_STAGE_BYTES);
        uint32_t bBase = aBase + G_A_BYTES;

#pragma unroll
        for (int ks = 0; ks < 4; ks++) {
            uint32_t kb = (uint32_t)(ks * 16 * 2);
            uint32_t af[2][4];
            ldsm_x4(af[0][0], af[0][1], af[0][2], af[0][3], aBase + offA0 + kb);
            ldsm_x4(af[1][0], af[1][1], af[1][2], af[1][3], aBase + offA1 + kb);
            uint32_t bf[8][2];
#pragma unroll
            for (int tnp = 0; tnp < 4; tnp++)
                ldsm_x4(bf[2 * tnp][0], bf[2 * tnp][1],
                        bf[2 * tnp + 1][0], bf[2 * tnp + 1][1],
                        bBase + offB[tnp] + kb);
#pragma unroll
            for (int tm = 0; tm < 2; tm++)
#pragma unroll
                for (int tn = 0; tn < 8; tn++)
                    mma_f16(acc[tm][tn], af[tm], bf[tn]);
        }
    }

    // epilogue (c-fragment: lane -> row l/4, cols 2*(l%4))
#pragma unroll
    for (int tm = 0; tm < 2; tm++) {
#pragma unroll
        for (int half = 0; half < 2; half++) {
            int m = m0 + wm * 32 + tm * 16 + half * 8 + r_lo;
            if (m >= M) continue;
#pragma unroll
            for (int tn = 0; tn < 8; tn++) {
                int n = n0 + wn * 64 + tn * 8 + k_lo * 2;
                float2 o;
                o.x = acc[tm][tn][half * 2 + 0];
                o.y = acc[tm][tn][half * 2 + 1];
                if (split_n) {
                    if (n < split_n) {
                        *(__half2*)(Cph + (size_t)m * split_n + n) =
                            __floats2half2_rn(o.x, o.y);
                    } else {
                        int n2 = n - split_n;
                        float2 bb = *(const float2*)(bias + n2);
                        o.x += bb.x; o.y += bb.y;
                        *(float2*)(C2 + (size_t)m * split_n + n2) = o;
                    }
                    continue;
                }
                if (bias) {
                    float2 bv = *(const float2*)(bias + n);
                    o.x += bv.x; o.y += bv.y;
                }
                if (relu) {
                    o.x = fmaxf(o.x, 0.f);
                    o.y = fmaxf(o.y, 0.f);
                }
                if (half_out) {
                    *(__half2*)(Ch + (size_t)m * N + n) = __floats2half2_rn(o.x, o.y);
                } else {
                    *(float2*)(C + (size_t)m * N + n) = o;
                }
            }
        }
    }
}

// ---------------- launcher -----------------------------------------------------
extern "C" void kernel_launch(void* const* d_in, const int* in_sizes, int n_in,
                              void* d_out, int out_size) {
    const float* x   = (const float*)d_in[0];
    const int*   ei  = (const int*)d_in[1];   // int32 OR int64 (device-detected)
    const float* W1l = (const float*)d_in[2];
    const float* b1  = (const float*)d_in[3];
    const float* W1r = (const float*)d_in[4];
    const float* W2l = (const float*)d_in[5];
    const float* b2  = (const float*)d_in[6];
    const float* W2r = (const float*)d_in[7];
    float* out = (float*)d_out;

    int* cnt;
    __half *xr, *aggA, *h, *p, *Wt1l, *Wt1r, *Wt2lr;
    float* q;
    cudaGetSymbolAddress((void**)&cnt,   g_cnt);
    cudaGetSymbolAddress((void**)&xr,    g_xr);
    cudaGetSymbolAddress((void**)&aggA,  g_aggA);
    cudaGetSymbolAddress((void**)&h,     g_h);
    cudaGetSymbolAddress((void**)&p,     g_p);
    cudaGetSymbolAddress((void**)&q,     g_q);
    cudaGetSymbolAddress((void**)&Wt1l,  g_Wt1l);
    cudaGetSymbolAddress((void**)&Wt1r,  g_Wt1r);
    cudaGetSymbolAddress((void**)&Wt2lr, g_Wt2lr);

    static int smem_set = 0;
    if (!smem_set) {
        cudaFuncSetAttribute(gemm_fp16_kernel,
                             cudaFuncAttributeMaxDynamicSharedMemorySize, G_SMEM_SZ);
        smem_set = 1;
    }

    // CSR build: memset node + 3 kernels
    cudaMemsetAsync(cnt, 0, NN * sizeof(int));
    hist_kernel<<<(EE + 255) / 256, 256>>>(ei);
    scan_fused<<<SCAN_BLOCKS, 256>>>();
    fill_kernel<<<(EE + 255) / 256, 256>>>(ei);

    // Layer 1 aggregation (+ fused fp16 conversion of x)
    agg1_kernel<<<(NN + 7) / 8, 256>>>(x, aggA, xr);

    // fp16 weights
    prep_weights<<<(PREP_TOT + 255) / 256, 256>>>(W1l, W1r, W2l, W2r);

    // Layer 1 GEMM: h = relu(aggA@W1l + xr@W1r + b1), fp16 out
    {
        dim3 grid(FHID / G_BN, (NN + G_BM - 1) / G_BM);
        gemm_fp16_kernel<<<grid, 512, G_SMEM_SZ>>>(
            aggA, Wt1l, FIN, xr, Wt1r, FIN, b1, nullptr, h, nullptr, nullptr,
            NN, FHID, 1, 1, 0);
    }
    // Layer 2 fused GEMM: cols 0-255 -> p (fp16), cols 256-511 -> q = h@W2r + b2
    {
        dim3 grid((2 * FOUT) / G_BN, (NN + G_BM - 1) / G_BM);
        gemm_fp16_kernel<<<grid, 512, G_SMEM_SZ>>>(
            h, Wt2lr, FHID, nullptr, nullptr, 0, b2, nullptr, nullptr, p, q,
            NN, 2 * FOUT, 0, 0, FOUT);
    }
    // out = scatter_mean(p_fp16) + q
    agg2_kernel<<<(NN + 7) / 8, 256>>>(p, q, out);
}

// round 16
// speedup vs baseline: 1.5077x; 1.0091x over previous
#include <cuda_runtime.h>
#include <cuda_fp16.h>
#include <cstdint>

// Problem constants (fixed by the dataset generator).
#define NN   40000
#define EE   640000
#define FIN  128
#define FHID 512
#define FOUT 256

#define SCAN_BLOCKS ((NN + 255) / 256)   // 157

// ---------------- scratch (static device globals; no allocation allowed) ----
__device__ int    g_is64;
__device__ int    g_cnt[NN];
__device__ int    g_rowptr[NN + 1];
__device__ int    g_cursor[NN];
__device__ int    g_col[EE];
__device__ __half g_xr  [(size_t)NN * FIN];   // fp16 copy of x           (10 MB)
__device__ __half g_aggA[(size_t)NN * FIN];   // fp16 mean-aggregated x   (10 MB)
__device__ __half g_h   [(size_t)NN * FHID];  // fp16 layer-1 output      (41 MB)
__device__ __half g_p   [(size_t)NN * FOUT];  // h @ W2l, fp16            (20 MB)
__device__ __half g_q   [(size_t)NN * FOUT];  // h @ W2r + b2, fp16       (20 MB)
// transposed fp16 weights [N,K]
__device__ __half g_Wt1l[FHID * FIN];
__device__ __half g_Wt1r[FHID * FIN];
__device__ __half g_Wt2lr[2 * FOUT * FHID];   // rows 0-255: W2l^T, 256-511: W2r^T

__device__ __forceinline__ int edge_at(const int* __restrict__ ei, int is64, size_t idx) {
    return is64 ? (int)((const long long*)ei)[idx] : ei[idx];
}

// ---------------- CSR build --------------------------------------------------
__device__ __forceinline__ int detect_is64(const int* __restrict__ ei32) {
    int all0 = 1;
#pragma unroll
    for (int k = 0; k < 64; k++)
        if (__ldg(&ei32[2 * k + 1]) != 0) all0 = 0;
    return all0;
}
// 2 edges per thread.
__global__ void hist_kernel(const int* __restrict__ ei) {
    __shared__ int s_is64;
    if (threadIdx.x == 0) s_is64 = detect_is64(ei);
    __syncthreads();
    int is64 = s_is64;
    if (blockIdx.x == 0 && threadIdx.x == 0) g_is64 = is64;
    int e = (blockIdx.x * blockDim.x + threadIdx.x) * 2;
    if (e < EE) {
        atomicAdd(&g_cnt[edge_at(ei, is64, (size_t)EE + e)], 1);
        if (e + 1 < EE)
            atomicAdd(&g_cnt[edge_at(ei, is64, (size_t)EE + e + 1)], 1);
    }
}

__global__ void scan_fused() {
    __shared__ int red[256];
    __shared__ int sh[256];
    int b = blockIdx.x, t = threadIdx.x;

    int lim = b * 256;
    int pre = 0;
    for (int i = t; i < lim; i += 256) pre += g_cnt[i];
    red[t] = pre;
    __syncthreads();
    for (int off = 128; off > 0; off >>= 1) {
        if (t < off) red[t] += red[t + off];
        __syncthreads();
    }
    int blockoff = red[0];

    int i = lim + t;
    int v = (i < NN) ? g_cnt[i] : 0;
    sh[t] = v;
    __syncthreads();
    for (int off = 1; off < 256; off <<= 1) {
        int u = (t >= off) ? sh[t - off] : 0;
        __syncthreads();
        sh[t] += u;
        __syncthreads();
    }
    int excl = sh[t] - v + blockoff;
    if (i < NN) {
        g_rowptr[i] = excl;
        g_cursor[i] = excl;
    }
    if (b == 0 && t == 0) g_rowptr[NN] = EE;
}

// 2 edges per thread.
__global__ void fill_kernel(const int* __restrict__ ei) {
    int is64 = g_is64;
    int e = (blockIdx.x * blockDim.x + threadIdx.x) * 2;
    if (e < EE) {
        int d = edge_at(ei, is64, (size_t)EE + e);
        int s = edge_at(ei, is64, (size_t)e);
        g_col[atomicAdd(&g_cursor[d], 1)] = s;
        if (e + 1 < EE) {
            int d1 = edge_at(ei, is64, (size_t)EE + e + 1);
            int s1 = edge_at(ei, is64, (size_t)e + 1);
            g_col[atomicAdd(&g_cursor[d1], 1)] = s1;
        }
    }
}

// ---------------- fused prep: weight transpose + fp16, and x -> xr ------------
#define W1_ELEMS (FIN * FHID)
#define W2_ELEMS (FHID * FOUT)
#define X4_ELEMS (NN * FIN / 4)
#define PREP_TOT (2 * W1_ELEMS + 2 * W2_ELEMS + X4_ELEMS)
__global__ void prep_all(const float* __restrict__ W1l, const float* __restrict__ W1r,
                         const float* __restrict__ W2l, const float* __restrict__ W2r,
                         const float* __restrict__ x, __half* __restrict__ xr) {
    int idx = blockIdx.x * blockDim.x + threadIdx.x;
    if (idx < W1_ELEMS) {
        int k = idx / FHID, n = idx % FHID;
        g_Wt1l[(size_t)n * FIN + k] = __float2half_rn(W1l[idx]);
        return;
    }
    idx -= W1_ELEMS;
    if (idx < W1_ELEMS) {
        int k = idx / FHID, n = idx % FHID;
        g_Wt1r[(size_t)n * FIN + k] = __float2half_rn(W1r[idx]);
        return;
    }
    idx -= W1_ELEMS;
    if (idx < W2_ELEMS) {
        int k = idx / FOUT, n = idx % FOUT;
        g_Wt2lr[(size_t)n * FHID + k] = __float2half_rn(W2l[idx]);
        return;
    }
    idx -= W2_ELEMS;
    if (idx < W2_ELEMS) {
        int k = idx / FOUT, n = idx % FOUT;
        g_Wt2lr[(size_t)(n + FOUT) * FHID + k] = __float2half_rn(W2r[idx]);
        return;
    }
    idx -= W2_ELEMS;
    if (idx < X4_ELEMS) {
        float4 v = *(const float4*)(x + (size_t)idx * 4);
        uint2 o;
        *(__half2*)&o.x = __floats2half2_rn(v.x, v.y);
        *(__half2*)&o.y = __floats2half2_rn(v.z, v.w);
        *(uint2*)(xr + (size_t)idx * 4) = o;
    }
}

// ---------------- layer-1 aggregation (warp per node, fp16 gather) ------------
// Row of xr = 128 halves = 256 B = 32 uint2; lane owns one uint2 (4 halves).
// fp32 accumulate; mean written as fp16 (aggA).
__global__ void __launch_bounds__(256)
agg1_kernel(const __half* __restrict__ xr, __half* __restrict__ aggA) {
    int node = blockIdx.x * (blockDim.x >> 5) + (threadIdx.x >> 5);
    if (node >= NN) return;
    int lane = threadIdx.x & 31;
    int beg = g_rowptr[node];
    int end = g_rowptr[node + 1];

    const uint2* fb = (const uint2*)xr;   // row = 32 uint2
    float acc[4] = {0.f, 0.f, 0.f, 0.f};

    auto accum = [&](uint2 u) {
        float2 f0 = __half22float2(*(const __half2*)&u.x);
        float2 f1 = __half22float2(*(const __half2*)&u.y);
        acc[0] += f0.x; acc[1] += f0.y;
        acc[2] += f1.x; acc[3] += f1.y;
    };

    int j = beg;
    for (; j + 3 < end; j += 4) {
        int s0 = __ldg(&g_col[j + 0]);
        int s1 = __ldg(&g_col[j + 1]);
        int s2 = __ldg(&g_col[j + 2]);
        int s3 = __ldg(&g_col[j + 3]);
        uint2 u0 = fb[(size_t)s0 * 32 + lane];
        uint2 u1 = fb[(size_t)s1 * 32 + lane];
        uint2 u2 = fb[(size_t)s2 * 32 + lane];
        uint2 u3 = fb[(size_t)s3 * 32 + lane];
        accum(u0); accum(u1); accum(u2); accum(u3);
    }
    for (; j < end; j++) {
        int s0 = __ldg(&g_col[j]);
        accum(fb[(size_t)s0 * 32 + lane]);
    }
    float inv = 1.0f / (float)max(end - beg, 1);
    uint2 o;
    *(__half2*)&o.x = __floats2half2_rn(acc[0] * inv, acc[1] * inv);
    *(__half2*)&o.y = __floats2half2_rn(acc[2] * inv, acc[3] * inv);
    ((uint2*)aggA)[(size_t)node * 32 + lane] = o;
}

// ---------------- layer-2 aggregation (warp per node, fp16 gather, +q) --------
// Row of p and q = 256 halves = 512 B = 32 uint4; lane owns one uint4 (8 halves).
// fp32 accumulate; out fp32.
__global__ void __launch_bounds__(256)
agg2_kernel(const __half* __restrict__ p, const __half* __restrict__ q,
            float* __restrict__ out) {
    int node = blockIdx.x * (blockDim.x >> 5) + (threadIdx.x >> 5);
    if (node >= NN) return;
    int lane = threadIdx.x & 31;
    int beg = g_rowptr[node];
    int end = g_rowptr[node + 1];

    const uint4* fb = (const uint4*)p;   // row = 32 uint4
    float acc[8];
#pragma unroll
    for (int i = 0; i < 8; i++) acc[i] = 0.f;

    auto accum = [&](uint4 u) {
        float2 f0 = __half22float2(*(const __half2*)&u.x);
        float2 f1 = __half22float2(*(const __half2*)&u.y);
        float2 f2 = __half22float2(*(const __half2*)&u.z);
        float2 f3 = __half22float2(*(const __half2*)&u.w);
        acc[0] += f0.x; acc[1] += f0.y;
        acc[2] += f1.x; acc[3] += f1.y;
        acc[4] += f2.x; acc[5] += f2.y;
        acc[6] += f3.x; acc[7] += f3.y;
    };

    int j = beg;
    for (; j + 3 < end; j += 4) {
        int s0 = __ldg(&g_col[j + 0]);
        int s1 = __ldg(&g_col[j + 1]);
        int s2 = __ldg(&g_col[j + 2]);
        int s3 = __ldg(&g_col[j + 3]);
        uint4 u0 = fb[(size_t)s0 * 32 + lane];
        uint4 u1 = fb[(size_t)s1 * 32 + lane];
        uint4 u2 = fb[(size_t)s2 * 32 + lane];
        uint4 u3 = fb[(size_t)s3 * 32 + lane];
        accum(u0); accum(u1); accum(u2); accum(u3);
    }
    for (; j < end; j++) {
        int s0 = __ldg(&g_col[j]);
        accum(fb[(size_t)s0 * 32 + lane]);
    }

    float inv = 1.0f / (float)max(end - beg, 1);
    // q row: lane owns same 8 halves; out: floats [lane*8, lane*8+8)
    uint4 qu = ((const uint4*)q)[(size_t)node * 32 + lane];
    float2 q0 = __half22float2(*(const __half2*)&qu.x);
    float2 q1 = __half22float2(*(const __half2*)&qu.y);
    float2 q2 = __half22float2(*(const __half2*)&qu.z);
    float2 q3 = __half22float2(*(const __half2*)&qu.w);
    float4* ov = (float4*)(out + (size_t)node * FOUT);
    float4 o0, o1;
    o0.x = acc[0] * inv + q0.x; o0.y = acc[1] * inv + q0.y;
    o0.z = acc[2] * inv + q1.x; o0.w = acc[3] * inv + q1.y;
    o1.x = acc[4] * inv + q2.x; o1.y = acc[5] * inv + q2.y;
    o1.z = acc[6] * inv + q3.x; o1.w = acc[7] * inv + q3.y;
    ov[2 * lane]     = o0;
    ov[2 * lane + 1] = o1;
}

// ================= fp16 mma.sync m16n8k16 GEMM, BM=128 x BN=256, 3-stage =====
#define G_BM 128
#define G_BN 256
#define G_BK 64                                // halves per k-tile
#define G_STAGES 3
#define G_STRIDE_H 72                          // halves per smem row (144 B)
#define G_A_BYTES (G_BM * G_STRIDE_H * 2)      // 18432
#define G_B_BYTES (G_BN * G_STRIDE_H * 2)      // 36864
#define G_STAGE_BYTES (G_A_BYTES + G_B_BYTES)  // 55296
#define G_SMEM_SZ (G_STAGES * G_STAGE_BYTES)   // 165888

__device__ __forceinline__ uint32_t smem_u32(const void* p) {
    uint32_t a;
    asm("{ .reg .u64 t; cvta.to.shared.u64 t, %1; cvt.u32.u64 %0, t; }"
        : "=r"(a) : "l"(p));
    return a;
}
__device__ __forceinline__ void cp_async16(uint32_t dst, const void* src, int src_bytes) {
    asm volatile("cp.async.ca.shared.global [%0], [%1], 16, %2;"
                 :: "r"(dst), "l"(src), "r"(src_bytes) : "memory");
}
__device__ __forceinline__ void cp_commit() {
    asm volatile("cp.async.commit_group;" ::: "memory");
}
template <int NPEND>
__device__ __forceinline__ void cp_wait() {
    asm volatile("cp.async.wait_group %0;" :: "n"(NPEND) : "memory");
}
__device__ __forceinline__ void mma_f16(float* d, const uint32_t* a, const uint32_t* b) {
    asm volatile(
        "mma.sync.aligned.m16n8k16.row.col.f32.f16.f16.f32 "
        "{%0,%1,%2,%3}, {%4,%5,%6,%7}, {%8,%9}, {%0,%1,%2,%3};"
        : "+f"(d[0]), "+f"(d[1]), "+f"(d[2]), "+f"(d[3])
        : "r"(a[0]), "r"(a[1]), "r"(a[2]), "r"(a[3]), "r"(b[0]), "r"(b[1]));
}
__device__ __forceinline__ void ldsm_x4(uint32_t& d0, uint32_t& d1, uint32_t& d2,
                                        uint32_t& d3, uint32_t addr) {
    asm volatile("ldmatrix.sync.aligned.m8n8.x4.shared.b16 {%0,%1,%2,%3}, [%4];"
                 : "=r"(d0), "=r"(d1), "=r"(d2), "=r"(d3) : "r"(addr));
}

template <int ROWS>
__device__ __forceinline__ void issue_tile(
    const __half* __restrict__ src, int row0, int row_lim, int K, int k0,
    uint32_t dst_base, int tid) {
#pragma unroll
    for (int u = 0; u < (ROWS * 8) / 512; u++) {
        int id  = u * 512 + tid;
        int row = id >> 3;
        int c   = id & 7;
        int gr  = row0 + row;
        int ok  = gr < row_lim;
        const __half* s = src + (size_t)(ok ? gr : (row_lim - 1)) * K + k0 + c * 8;
        cp_async16(dst_base + row * (G_STRIDE_H * 2) + c * 16, s, ok ? 16 : 0);
    }
}

// split_n == 0: fp16 Ch (half_out) with bias/relu in fp32.
// split_n  > 0: cols < split_n -> Cph (fp16, no bias),
//               cols >= split_n -> C2h (fp16, +bias[n-split_n] in fp32).
__global__ void __launch_bounds__(512, 1)
gemm_fp16_kernel(const __half* __restrict__ A1, const __half* __restrict__ B1t, int K1,
                 const __half* __restrict__ A2, const __half* __restrict__ B2t, int K2,
                 const float* __restrict__ bias,
                 __half* __restrict__ Ch,
                 __half* __restrict__ Cph, __half* __restrict__ C2h,
                 int M, int N, int relu, int split_n) {
    extern __shared__ char smem[];
    uint32_t sb = smem_u32(smem);

    int tid  = threadIdx.x;
    int lane = tid & 31;
    int wid  = tid >> 5;
    int wm   = wid & 3;
    int wn   = wid >> 2;
    int m0 = blockIdx.y * G_BM;
    int n0 = blockIdx.x * G_BN;

    const int kt1 = K1 / G_BK;
    const int KT  = kt1 + K2 / G_BK;

    float acc[2][8][4];
#pragma unroll
    for (int i = 0; i < 2; i++)
#pragma unroll
        for (int j = 0; j < 8; j++)
#pragma unroll
            for (int q = 0; q < 4; q++) acc[i][j][q] = 0.f;

    auto issue = [&](int kt) {
        const __half* A;
        const __half* B;
        int K, kk;
        if (kt < kt1) { A = A1; B = B1t; K = K1; kk = kt; }
        else          { A = A2; B = B2t; K = K2; kk = kt - kt1; }
        int s = kt % G_STAGES;
        uint32_t aB = sb + (uint32_t)(s * G_STAGE_BYTES);
        uint32_t bB = aB + G_A_BYTES;
        issue_tile<G_BM>(A, m0, M, K, kk * G_BK, aB, tid);
        issue_tile<G_BN>(B, n0, N, K, kk * G_BK, bB, tid);
    };

    issue(0);
    cp_commit();
    issue(1);
    cp_commit();

    int lrow = lane & 7;
    int arow = wm * 32 + ((lane & 8) ? 8 : 0) + lrow;
    int acol = (lane & 16) ? 8 : 0;
    uint32_t offA0 = (uint32_t)(arow * G_STRIDE_H + acol) * 2;
    uint32_t offA1 = (uint32_t)((arow + 16) * G_STRIDE_H + acol) * 2;
    int brow = wn * 64 + ((lane & 16) ? 8 : 0) + lrow;
    int bcol = (lane & 8) ? 8 : 0;
    uint32_t offB[4];
#pragma unroll
    for (int tnp = 0; tnp < 4; tnp++)
        offB[tnp] = (uint32_t)((brow + tnp * 16) * G_STRIDE_H + bcol) * 2;

    int r_lo = (lane >> 2);
    int k_lo = (lane & 3);

    for (int kt = 0; kt < KT; kt++) {
        if (kt + 1 < KT) cp_wait<1>();
        else             cp_wait<0>();
        __syncthreads();

        if (kt + 2 < KT) {
            issue(kt + 2);
            cp_commit();
        }

        int s = kt % G_STAGES;
        uint32_t aBase = sb + (uint32_t)(s * G_STAGE_BYTES);
        uint32_t bBase = aBase + G_A_BYTES;

#pragma unroll
        for (int ks = 0; ks < 4; ks++) {
            uint32_t kb = (uint32_t)(ks * 16 * 2);
            uint32_t af[2][4];
            ldsm_x4(af[0][0], af[0][1], af[0][2], af[0][3], aBase + offA0 + kb);
            ldsm_x4(af[1][0], af[1][1], af[1][2], af[1][3], aBase + offA1 + kb);
            uint32_t bf[8][2];
#pragma unroll
            for (int tnp = 0; tnp < 4; tnp++)
                ldsm_x4(bf[2 * tnp][0], bf[2 * tnp][1],
                        bf[2 * tnp + 1][0], bf[2 * tnp + 1][1],
                        bBase + offB[tnp] + kb);
#pragma unroll
            for (int tm = 0; tm < 2; tm++)
#pragma unroll
                for (int tn = 0; tn < 8; tn++)
                    mma_f16(acc[tm][tn], af[tm], bf[tn]);
        }
    }

    // epilogue (c-fragment: lane -> row l/4, cols 2*(l%4))
#pragma unroll
    for (int tm = 0; tm < 2; tm++) {
#pragma unroll
        for (int half = 0; half < 2; half++) {
            int m = m0 + wm * 32 + tm * 16 + half * 8 + r_lo;
            if (m >= M) continue;
#pragma unroll
            for (int tn = 0; tn < 8; tn++) {
                int n = n0 + wn * 64 + tn * 8 + k_lo * 2;
                float2 o;
                o.x = acc[tm][tn][half * 2 + 0];
                o.y = acc[tm][tn][half * 2 + 1];
                if (split_n) {
                    if (n < split_n) {
                        *(__half2*)(Cph + (size_t)m * split_n + n) =
                            __floats2half2_rn(o.x, o.y);
                    } else {
                        int n2 = n - split_n;
                        float2 bb = *(const float2*)(bias + n2);
                        *(__half2*)(C2h + (size_t)m * split_n + n2) =
                            __floats2half2_rn(o.x + bb.x, o.y + bb.y);
                    }
                    continue;
                }
                if (bias) {
                    float2 bv = *(const float2*)(bias + n);
                    o.x += bv.x; o.y += bv.y;
                }
                if (relu) {
                    o.x = fmaxf(o.x, 0.f);
                    o.y = fmaxf(o.y, 0.f);
                }
                *(__half2*)(Ch + (size_t)m * N + n) = __floats2half2_rn(o.x, o.y);
            }
        }
    }
}

// ---------------- launcher -----------------------------------------------------
extern "C" void kernel_launch(void* const* d_in, const int* in_sizes, int n_in,
                              void* d_out, int out_size) {
    const float* x   = (const float*)d_in[0];
    const int*   ei  = (const int*)d_in[1];   // int32 OR int64 (device-detected)
    const float* W1l = (const float*)d_in[2];
    const float* b1  = (const float*)d_in[3];
    const float* W1r = (const float*)d_in[4];
    const float* W2l = (const float*)d_in[5];
    const float* b2  = (const float*)d_in[6];
    const float* W2r = (const float*)d_in[7];
    float* out = (float*)d_out;

    int* cnt;
    __half *xr, *aggA, *h, *p, *q, *Wt1l, *Wt1r, *Wt2lr;
    cudaGetSymbolAddress((void**)&cnt,   g_cnt);
    cudaGetSymbolAddress((void**)&xr,    g_xr);
    cudaGetSymbolAddress((void**)&aggA,  g_aggA);
    cudaGetSymbolAddress((void**)&h,     g_h);
    cudaGetSymbolAddress((void**)&p,     g_p);
    cudaGetSymbolAddress((void**)&q,     g_q);
    cudaGetSymbolAddress((void**)&Wt1l,  g_Wt1l);
    cudaGetSymbolAddress((void**)&Wt1r,  g_Wt1r);
    cudaGetSymbolAddress((void**)&Wt2lr, g_Wt2lr);

    static int smem_set = 0;
    if (!smem_set) {
        cudaFuncSetAttribute(gemm_fp16_kernel,
                             cudaFuncAttributeMaxDynamicSharedMemorySize, G_SMEM_SZ);
        smem_set = 1;
    }

    // CSR build + prep: memset node + 4 kernels
    cudaMemsetAsync(cnt, 0, NN * sizeof(int));
    hist_kernel<<<(EE / 2 + 255) / 256, 256>>>(ei);                 // k1 (+detect)
    scan_fused<<<SCAN_BLOCKS, 256>>>();                             // k2
    prep_all<<<(PREP_TOT + 255) / 256, 256>>>(W1l, W1r, W2l, W2r, x, xr);  // k3
    fill_kernel<<<(EE / 2 + 255) / 256, 256>>>(ei);                 // k4 <- profiled

    // Layer 1 aggregation (fp16 gather from xr)
    agg1_kernel<<<(NN + 7) / 8, 256>>>(xr, aggA);

    // Layer 1 GEMM: h = relu(aggA@W1l + xr@W1r + b1), fp16 out
    {
        dim3 grid(FHID / G_BN, (NN + G_BM - 1) / G_BM);
        gemm_fp16_kernel<<<grid, 512, G_SMEM_SZ>>>(
            aggA, Wt1l, FIN, xr, Wt1r, FIN, b1, h, nullptr, nullptr,
            NN, FHID, 1, 0);
    }
    // Layer 2 fused GEMM: cols 0-255 -> p (fp16), cols 256-511 -> q (fp16, +b2)
    {
        dim3 grid((2 * FOUT) / G_BN, (NN + G_BM - 1) / G_BM);
        gemm_fp16_kernel<<<grid, 512, G_SMEM_SZ>>>(
            h, Wt2lr, FHID, nullptr, nullptr, 0, b2, nullptr, p, q,
            NN, 2 * FOUT, 0, FOUT);
    }
    // out = scatter_mean(p_fp16) + q_fp16   (fp32 accumulate + fp32 out)
    agg2_kernel<<<(NN + 7) / 8, 256>>>(p, q, out);
}